// round 3
// baseline (speedup 1.0000x reference)
#include <cuda_runtime.h>
#include <cuda_bf16.h>
#include <math.h>

// Problem constants
#define BATCH 131072
#define SD 64        // state dim
#define CD 16        // control dim
#define HID 256      // hidden
#define LDH 260      // padded smem row stride (floats)

// Scratch (allowed: __device__ globals, no runtime allocation)
__device__ float g_W3B[HID * CD];    // W3 @ Bmat  (256 x 16)
__device__ float g_b3B[CD];          // b3 @ Bmat
__device__ float g_pB[BATCH * CD];   // 8 MB intermediate pB
__device__ int   g_K;                // global while-loop iteration count

// ---------------------------------------------------------------------------
// Kernel 0: fold W3 @ Bmat (and b3 @ Bmat), reset g_K. 1 block x 256 threads.
// ---------------------------------------------------------------------------
__global__ void k_prep(const float* __restrict__ W3, const float* __restrict__ b3,
                       const float* __restrict__ Bm) {
    int h = threadIdx.x;            // one hidden row per thread (256)
    float acc[CD];
#pragma unroll
    for (int j = 0; j < CD; j++) acc[j] = 0.0f;
    for (int d = 0; d < SD; d++) {
        float w = W3[h * SD + d];
#pragma unroll
        for (int j = 0; j < CD; j++) acc[j] += w * Bm[d * CD + j];
    }
#pragma unroll
    for (int j = 0; j < CD; j++) g_W3B[h * CD + j] = acc[j];

    if (h < CD) {
        float a = 0.0f;
        for (int d = 0; d < SD; d++) a += b3[d] * Bm[d * CD + h];
        g_b3B[h] = a;
    }
    if (h == 0) g_K = 0;
}

// ---------------------------------------------------------------------------
// Fused MLP: per block, 64 rows. H tile + W chunk in dynamic smem.
// Thread layout: tr = tid/16 (row group of 4), tc = tid%16 (16 cols as 4 x float4).
// ---------------------------------------------------------------------------
__device__ __forceinline__ void gemm_chunks(
    float acc[4][16], const float* __restrict__ Wsrc, int Ktot,
    const float* __restrict__ H, float* __restrict__ Wb,
    int tr, int tc, int tid)
{
    for (int kc = 0; kc < Ktot; kc += 32) {
        __syncthreads();   // Wb free to overwrite; prior H writes visible
#pragma unroll
        for (int l = 0; l < 8; l++) {
            int idx = tid + l * 256;         // 2048 float4 = 32x256 floats
            int k = idx >> 6, c4 = idx & 63;
            *(float4*)&Wb[k * LDH + c4 * 4] =
                *(const float4*)&Wsrc[(kc + k) * HID + c4 * 4];
        }
        __syncthreads();
#pragma unroll 4
        for (int k = 0; k < 32; k++) {
            float a[4];
#pragma unroll
            for (int i = 0; i < 4; i++) a[i] = H[(tr * 4 + i) * LDH + kc + k];
#pragma unroll
            for (int q = 0; q < 4; q++) {
                float4 w = *(const float4*)&Wb[k * LDH + tc * 4 + 64 * q];
#pragma unroll
                for (int i = 0; i < 4; i++) {
                    acc[i][4 * q + 0] += a[i] * w.x;
                    acc[i][4 * q + 1] += a[i] * w.y;
                    acc[i][4 * q + 2] += a[i] * w.z;
                    acc[i][4 * q + 3] += a[i] * w.w;
                }
            }
        }
    }
}

__device__ __forceinline__ void store_relu(
    const float acc[4][16], const float* __restrict__ b,
    float* __restrict__ H, int tr, int tc)
{
    __syncthreads();   // everyone done reading H / Wb before overwrite
#pragma unroll
    for (int q = 0; q < 4; q++) {
        float4 bv = *(const float4*)&b[tc * 4 + 64 * q];
#pragma unroll
        for (int i = 0; i < 4; i++) {
            float4 h;
            h.x = fmaxf(acc[i][4 * q + 0] + bv.x, 0.0f);
            h.y = fmaxf(acc[i][4 * q + 1] + bv.y, 0.0f);
            h.z = fmaxf(acc[i][4 * q + 2] + bv.z, 0.0f);
            h.w = fmaxf(acc[i][4 * q + 3] + bv.w, 0.0f);
            *(float4*)&H[(tr * 4 + i) * LDH + tc * 4 + 64 * q] = h;
        }
    }
}

__global__ void __launch_bounds__(256, 2) k_mlp(
    const float* __restrict__ x, const float* __restrict__ t,
    const float* __restrict__ W1, const float* __restrict__ b1,
    const float* __restrict__ W2, const float* __restrict__ b2)
{
    extern __shared__ float sm[];
    float* H  = sm;               // 64 x 260
    float* Wb = sm + 64 * LDH;    // 32 x 260 (also reused flat for W3B)

    int tid = threadIdx.x;
    int tr = tid >> 4, tc = tid & 15;
    int row0 = blockIdx.x * 64;
    float t0 = t[0];

    // Load x tile into H[:, 0:64]
#pragma unroll
    for (int l = 0; l < 16; l++) {
        int idx = tid + l * 256;
        int r = idx >> 6, c = idx & 63;
        H[r * LDH + c] = x[(row0 + r) * SD + c];
    }

    // ---- Layer 1: relu([x|t] @ W1 + b1). t-column folded into accumulator init.
    float acc[4][16];
#pragma unroll
    for (int q = 0; q < 4; q++) {
        float4 w = *(const float4*)&W1[64 * HID + tc * 4 + 64 * q];  // W1 row 64 = t row
#pragma unroll
        for (int i = 0; i < 4; i++) {
            acc[i][4 * q + 0] = t0 * w.x;
            acc[i][4 * q + 1] = t0 * w.y;
            acc[i][4 * q + 2] = t0 * w.z;
            acc[i][4 * q + 3] = t0 * w.w;
        }
    }
    gemm_chunks(acc, W1, 64, H, Wb, tr, tc, tid);
    store_relu(acc, b1, H, tr, tc);

    // ---- Layer 2: relu(H1 @ W2 + b2)
#pragma unroll
    for (int i = 0; i < 4; i++)
#pragma unroll
        for (int j = 0; j < 16; j++) acc[i][j] = 0.0f;
    gemm_chunks(acc, W2, 256, H, Wb, tr, tc, tid);
    store_relu(acc, b2, H, tr, tc);

    // ---- Layer 3: pB = H2 @ W3B + b3B   (output 64 x 16)
    __syncthreads();   // H2 writes visible; Wb free
    // Copy FULL W3B (256*16 = 4096 floats = 1024 float4). [R2 fix: previous
    // version copied only 1024 floats -> 3/4 of Wb was stale W2 data.]
#pragma unroll
    for (int l = 0; l < 4; l++) {
        int idx = tid + l * 256;          // 0..1023 float4 groups
        *(float4*)&Wb[idx * 4] = *(const float4*)&g_W3B[idx * 4];
    }
    __syncthreads();
    {
        int r  = tid >> 2;
        int j0 = (tid & 3) * 4;
        float4 a = make_float4(0.f, 0.f, 0.f, 0.f);
#pragma unroll 8
        for (int k = 0; k < HID; k++) {
            float h = H[r * LDH + k];
            float4 w = *(const float4*)&Wb[k * CD + j0];
            a.x += h * w.x; a.y += h * w.y; a.z += h * w.z; a.w += h * w.w;
        }
        float4 bb = *(const float4*)&g_b3B[j0];
        a.x += bb.x; a.y += bb.y; a.z += bb.z; a.w += bb.w;
        *(float4*)&g_pB[(row0 + r) * CD + j0] = a;
    }
}

// ---------------------------------------------------------------------------
// Per-row while-loop replication to find K_row; global max -> g_K.
// Exact JAX arithmetic: un = u - 0.1f*(u+pb) (no contraction), clamp,
// res = sqrt(sum d^2)/0.1f, continue while res >= 0.01f && i < 200.
// ---------------------------------------------------------------------------
__global__ void k_count() {
    int row = blockIdx.x * 256 + threadIdx.x;
    const float4* pbp = (const float4*)&g_pB[row * CD];
    float pb[16], u[16];
#pragma unroll
    for (int q = 0; q < 4; q++) {
        float4 v = pbp[q];
        pb[4 * q + 0] = v.x; pb[4 * q + 1] = v.y; pb[4 * q + 2] = v.z; pb[4 * q + 3] = v.w;
    }
#pragma unroll
    for (int j = 0; j < 16; j++) u[j] = 0.0f;

    int i = 0;
    float res = __int_as_float(0x7f800000);   // +inf
    while (res >= 0.01f && i < 200) {
        float s2 = 0.0f;
#pragma unroll
        for (int j = 0; j < 16; j++) {
            float s  = u[j] + pb[j];
            float un = __fsub_rn(u[j], __fmul_rn(0.1f, s));
            un = fminf(fmaxf(un, -1.0f), 1.0f);
            float d = un - u[j];
            s2 += d * d;
            u[j] = un;
        }
        res = __fdiv_rn(sqrtf(s2), 0.1f);
        i++;
    }
    // warp max, then one atomic per warp
    int v = i;
#pragma unroll
    for (int o = 16; o > 0; o >>= 1)
        v = max(v, __shfl_xor_sync(0xffffffffu, v, o));
    if ((threadIdx.x & 31) == 0) atomicMax(&g_K, v);
}

// ---------------------------------------------------------------------------
// Final: K iterations (fixed point) + TRACKED_ITERS+1 = 6 more, write out.
// ---------------------------------------------------------------------------
__global__ void k_final(float* __restrict__ out) {
    int row = blockIdx.x * 256 + threadIdx.x;
    const float4* pbp = (const float4*)&g_pB[row * CD];
    float pb[16], u[16];
#pragma unroll
    for (int q = 0; q < 4; q++) {
        float4 v = pbp[q];
        pb[4 * q + 0] = v.x; pb[4 * q + 1] = v.y; pb[4 * q + 2] = v.z; pb[4 * q + 3] = v.w;
    }
#pragma unroll
    for (int j = 0; j < 16; j++) u[j] = 0.0f;

    int total = g_K + 6;
    for (int it = 0; it < total; it++) {
#pragma unroll
        for (int j = 0; j < 16; j++) {
            float s  = u[j] + pb[j];
            float un = __fsub_rn(u[j], __fmul_rn(0.1f, s));
            u[j] = fminf(fmaxf(un, -1.0f), 1.0f);
        }
    }
    float4* op = (float4*)&out[row * CD];
#pragma unroll
    for (int q = 0; q < 4; q++) {
        float4 v;
        v.x = u[4 * q + 0]; v.y = u[4 * q + 1]; v.z = u[4 * q + 2]; v.w = u[4 * q + 3];
        op[q] = v;
    }
}

// ---------------------------------------------------------------------------
extern "C" void kernel_launch(void* const* d_in, const int* in_sizes, int n_in,
                              void* d_out, int out_size) {
    const float* x  = (const float*)d_in[0];
    const float* t  = (const float*)d_in[1];
    const float* W1 = (const float*)d_in[2];
    const float* b1 = (const float*)d_in[3];
    const float* W2 = (const float*)d_in[4];
    const float* b2 = (const float*)d_in[5];
    const float* W3 = (const float*)d_in[6];
    const float* b3 = (const float*)d_in[7];
    const float* Bm = (const float*)d_in[8];
    float* out = (float*)d_out;

    const int smem_bytes = (64 * LDH + 32 * LDH) * sizeof(float);  // 99,840 B
    cudaFuncSetAttribute(k_mlp, cudaFuncAttributeMaxDynamicSharedMemorySize, smem_bytes);

    k_prep<<<1, 256>>>(W3, b3, Bm);
    k_mlp<<<BATCH / 64, 256, smem_bytes>>>(x, t, W1, b1, W2, b2);
    k_count<<<BATCH / 256, 256>>>();
    k_final<<<BATCH / 256, 256>>>(out);
}

// round 6
// speedup vs baseline: 2.1902x; 2.1902x over previous
#include <cuda_runtime.h>
#include <cuda_bf16.h>
#include <math.h>
#include <cstdint>

#define BATCH 131072
#define SD 64
#define CD 16
#define HID 256

// ---------------- smem layout (bytes) ----------------
#define SM_A2H   0         // 128 rows x 264 halves (528B stride) = 67584
#define SM_A2L   67584
#define SM_WH    135168    // 256 n-rows x 72 halves (144B stride) = 36864
#define SM_WL    172032
#define SM_W3H   135168    // reuse W buffer: 16 x 264 halves (528B) = 8448
#define SM_W3L   143616
#define SM_B1    208896    // 256 f32
#define SM_B2    209920    // 256 f32
#define SM_B3B   210944    // 16 f32
#define SM_TOTAL 211008

// ---------------- scratch globals ----------------
__device__ float g_W3B[HID * CD];
__device__ float g_b3B[CD];
__device__ float g_pB[BATCH * CD];
__device__ int   g_K;

// ---------------- helpers ----------------
__device__ __forceinline__ uint32_t smem_u32(const void* p) {
    uint32_t a;
    asm("{ .reg .u64 t; cvta.to.shared.u64 t, %1; cvt.u32.u64 %0, t; }" : "=r"(a) : "l"(p));
    return a;
}

// split (a,b) f32 pair into packed bf16x2 hi + lo (residual)
__device__ __forceinline__ void split2(float a, float b, uint32_t& hi, uint32_t& lo) {
    __nv_bfloat16 ha = __float2bfloat16(a), hb = __float2bfloat16(b);
    float ra = a - __bfloat162float(ha);
    float rb = b - __bfloat162float(hb);
    __nv_bfloat16 la = __float2bfloat16(ra), lb = __float2bfloat16(rb);
    hi = ((uint32_t)__bfloat16_as_ushort(hb) << 16) | (uint32_t)__bfloat16_as_ushort(ha);
    lo = ((uint32_t)__bfloat16_as_ushort(lb) << 16) | (uint32_t)__bfloat16_as_ushort(la);
}

#define LDSM4(v, addr) \
    asm volatile("ldmatrix.sync.aligned.m8n8.x4.shared.b16 {%0,%1,%2,%3}, [%4];" \
        : "=r"((v)[0]), "=r"((v)[1]), "=r"((v)[2]), "=r"((v)[3]) : "r"(addr))

#define MMA(d, a, b0, b1) \
    asm volatile("mma.sync.aligned.m16n8k16.row.col.f32.bf16.bf16.f32 " \
        "{%0,%1,%2,%3}, {%4,%5,%6,%7}, {%8,%9}, {%0,%1,%2,%3};" \
        : "+f"((d)[0]), "+f"((d)[1]), "+f"((d)[2]), "+f"((d)[3]) \
        : "r"((a)[0]), "r"((a)[1]), "r"((a)[2]), "r"((a)[3]), "r"(b0), "r"(b1))

// ---------------- k_prep ----------------
__global__ void k_prep(const float* __restrict__ W3, const float* __restrict__ b3,
                       const float* __restrict__ Bm) {
    int h = threadIdx.x;
    float acc[CD];
#pragma unroll
    for (int j = 0; j < CD; j++) acc[j] = 0.0f;
    for (int d = 0; d < SD; d++) {
        float w = W3[h * SD + d];
#pragma unroll
        for (int j = 0; j < CD; j++) acc[j] += w * Bm[d * CD + j];
    }
#pragma unroll
    for (int j = 0; j < CD; j++) g_W3B[h * CD + j] = acc[j];
    if (h < CD) {
        float a = 0.0f;
        for (int d = 0; d < SD; d++) a += b3[d] * Bm[d * CD + h];
        g_b3B[h] = a;
    }
    if (h == 0) g_K = 0;
}

// coop: stage W chunk [64 k x 256 n] (f32 row-major gmem) -> Wt[n][k] bf16 hi/lo
__device__ __forceinline__ void load_wchunk(char* sm, const float* __restrict__ W,
                                            int krow0, int tid) {
    int n = tid;
#pragma unroll
    for (int it = 0; it < 8; it++) {
        int kb = krow0 + it * 8;
        uint32_t h[4], l[4];
#pragma unroll
        for (int q = 0; q < 4; q++) {
            float w0 = W[(kb + 2 * q) * HID + n];
            float w1 = W[(kb + 2 * q + 1) * HID + n];
            split2(w0, w1, h[q], l[q]);
        }
        *(uint4*)(sm + SM_WH + n * 144 + it * 16) = make_uint4(h[0], h[1], h[2], h[3]);
        *(uint4*)(sm + SM_WL + n * 144 + it * 16) = make_uint4(l[0], l[1], l[2], l[3]);
    }
}

// ---------------- fused MLP via mma.sync (HMMA) ----------------
__global__ void __launch_bounds__(256, 1) k_mlp(
    const float* __restrict__ x, const float* __restrict__ t,
    const float* __restrict__ W1, const float* __restrict__ b1,
    const float* __restrict__ W2, const float* __restrict__ b2)
{
    extern __shared__ char sm[];
    uint32_t smb = smem_u32(sm);
    int tid = threadIdx.x, wid = tid >> 5, lid = tid & 31;
    int slab = wid * 16;
    int row0 = blockIdx.x * 128;
    int r0 = lid >> 2, cq = 2 * (lid & 3);

    // coop: biases + W1 chunk
    float t0 = t[0];
    ((float*)(sm + SM_B1))[tid] = fmaf(t0, W1[64 * HID + tid], b1[tid]);
    ((float*)(sm + SM_B2))[tid] = b2[tid];
    if (tid < CD) ((float*)(sm + SM_B3B))[tid] = g_b3B[tid];
    load_wchunk(sm, W1, 0, tid);

    // per-warp: stage own 16 rows of X (f32) into own A2H slab region, stride 68 f32
    float* Xs = (float*)(sm + SM_A2H + wid * 8448);
#pragma unroll
    for (int i = 0; i < 8; i++) {
        int fid = i * 32 + lid;
        int r = fid >> 4, c4 = fid & 15;
        float4 v = *(const float4*)&x[(row0 + slab + r) * SD + c4 * 4];
        *(float4*)&Xs[r * 68 + c4 * 4] = v;
    }
    __syncwarp();

    // X fragments (hi/lo) in regs: 4 k-tiles
    uint32_t xh[4][4], xl[4][4];
#pragma unroll
    for (int kt = 0; kt < 4; kt++) {
        int cb = kt * 16 + cq;
        float2 v00 = *(float2*)&Xs[r0 * 68 + cb];
        float2 v10 = *(float2*)&Xs[(r0 + 8) * 68 + cb];
        float2 v01 = *(float2*)&Xs[r0 * 68 + cb + 8];
        float2 v11 = *(float2*)&Xs[(r0 + 8) * 68 + cb + 8];
        split2(v00.x, v00.y, xh[kt][0], xl[kt][0]);
        split2(v10.x, v10.y, xh[kt][1], xl[kt][1]);
        split2(v01.x, v01.y, xh[kt][2], xl[kt][2]);
        split2(v11.x, v11.y, xh[kt][3], xl[kt][3]);
    }
    __syncwarp();
    __syncthreads();   // W1 + biases staged; X frag loads done (X region freed)

    // ---- Layer 1: D[16x256] = X @ W1 (3-product) ----
    float d[32][4];
#pragma unroll
    for (int m = 0; m < 32; m++)
#pragma unroll
        for (int q = 0; q < 4; q++) d[m][q] = 0.0f;

#pragma unroll
    for (int kt = 0; kt < 4; kt++) {
#pragma unroll
        for (int n2 = 0; n2 < 16; n2++) {
            uint32_t bh[4], bl[4];
            uint32_t brow = n2 * 16 + ((lid >> 4) << 3) + (lid & 7);
            uint32_t baddr = smb + SM_WH + brow * 144 + (kt * 16 + (lid & 8)) * 2;
            LDSM4(bh, baddr);
            LDSM4(bl, baddr + (SM_WL - SM_WH));
            MMA(d[2 * n2],     xh[kt], bh[0], bh[1]);
            MMA(d[2 * n2],     xh[kt], bl[0], bl[1]);
            MMA(d[2 * n2],     xl[kt], bh[0], bh[1]);
            MMA(d[2 * n2 + 1], xh[kt], bh[2], bh[3]);
            MMA(d[2 * n2 + 1], xh[kt], bl[2], bl[3]);
            MMA(d[2 * n2 + 1], xl[kt], bh[2], bh[3]);
        }
    }

    // ---- relu + bias1 -> A2 (warp-private smem, hi/lo) ----
    {
        const float* bs1 = (const float*)(sm + SM_B1);
#pragma unroll
        for (int m = 0; m < 32; m++) {
            int c = m * 8 + cq;
            float2 bv = *(const float2*)&bs1[c];
            float h0 = fmaxf(d[m][0] + bv.x, 0.0f);
            float h1 = fmaxf(d[m][1] + bv.y, 0.0f);
            float h2 = fmaxf(d[m][2] + bv.x, 0.0f);
            float h3 = fmaxf(d[m][3] + bv.y, 0.0f);
            uint32_t hi01, lo01, hi23, lo23;
            split2(h0, h1, hi01, lo01);
            split2(h2, h3, hi23, lo23);
            int ra = slab + r0;
            *(uint32_t*)(sm + SM_A2H + ra * 528 + c * 2) = hi01;
            *(uint32_t*)(sm + SM_A2L + ra * 528 + c * 2) = lo01;
            *(uint32_t*)(sm + SM_A2H + (ra + 8) * 528 + c * 2) = hi23;
            *(uint32_t*)(sm + SM_A2L + (ra + 8) * 528 + c * 2) = lo23;
        }
    }
    __syncthreads();   // layer1 done everywhere; W buffer free; A2 visible

    // zero accum for layer 2
#pragma unroll
    for (int m = 0; m < 32; m++)
#pragma unroll
        for (int q = 0; q < 4; q++) d[m][q] = 0.0f;

    // ---- Layer 2: 4 K-chunks of 64 ----
#pragma unroll 1
    for (int kc = 0; kc < 4; kc++) {
        load_wchunk(sm, W2, kc * 64, tid);
        __syncthreads();
#pragma unroll
        for (int kt = 0; kt < 4; kt++) {
            uint32_t ah[4], al[4];
            uint32_t arow = slab + (lid & 15);
            uint32_t acol = kc * 64 + kt * 16 + ((lid >> 4) << 3);
            uint32_t aaddr = smb + SM_A2H + arow * 528 + acol * 2;
            LDSM4(ah, aaddr);
            LDSM4(al, aaddr + (SM_A2L - SM_A2H));
#pragma unroll
            for (int n2 = 0; n2 < 16; n2++) {
                uint32_t bh[4], bl[4];
                uint32_t brow = n2 * 16 + ((lid >> 4) << 3) + (lid & 7);
                uint32_t baddr = smb + SM_WH + brow * 144 + (kt * 16 + (lid & 8)) * 2;
                LDSM4(bh, baddr);
                LDSM4(bl, baddr + (SM_WL - SM_WH));
                MMA(d[2 * n2],     ah, bh[0], bh[1]);
                MMA(d[2 * n2],     ah, bl[0], bl[1]);
                MMA(d[2 * n2],     al, bh[0], bh[1]);
                MMA(d[2 * n2 + 1], ah, bh[2], bh[3]);
                MMA(d[2 * n2 + 1], ah, bl[2], bl[3]);
                MMA(d[2 * n2 + 1], al, bh[2], bh[3]);
            }
        }
        __syncthreads();
    }

    // ---- stage W3B^T [16n x 256k] hi/lo into W buffer ----
#pragma unroll
    for (int it = 0; it < 8; it++) {
        int pid = tid + it * 256;          // 2048 (n, k-pair) items
        int n = pid & 15, k2 = pid >> 4;   // k2 0..127
        float v0 = g_W3B[(2 * k2) * CD + n];
        float v1 = g_W3B[(2 * k2 + 1) * CD + n];
        uint32_t hi, lo;
        split2(v0, v1, hi, lo);
        *(uint32_t*)(sm + SM_W3H + n * 528 + k2 * 4) = hi;
        *(uint32_t*)(sm + SM_W3L + n * 528 + k2 * 4) = lo;
    }
    __syncthreads();

    // ---- relu + bias2 -> A3 fragments in regs ----
    uint32_t a3h[16][4], a3l[16][4];
    {
        const float* bs2 = (const float*)(sm + SM_B2);
#pragma unroll
        for (int g = 0; g < 16; g++) {
#pragma unroll
            for (int hh = 0; hh < 2; hh++) {
                int m = 2 * g + hh;
                int c = m * 8 + cq;
                float2 bv = *(const float2*)&bs2[c];
                float h0 = fmaxf(d[m][0] + bv.x, 0.0f);
                float h1 = fmaxf(d[m][1] + bv.y, 0.0f);
                float h2 = fmaxf(d[m][2] + bv.x, 0.0f);
                float h3 = fmaxf(d[m][3] + bv.y, 0.0f);
                split2(h0, h1, a3h[g][2 * hh],     a3l[g][2 * hh]);
                split2(h2, h3, a3h[g][2 * hh + 1], a3l[g][2 * hh + 1]);
            }
        }
    }

    // ---- Layer 3: pB[16x16] = H2 @ W3B ----
    float d3a[4] = {0.f, 0.f, 0.f, 0.f};
    float d3b[4] = {0.f, 0.f, 0.f, 0.f};
#pragma unroll
    for (int g = 0; g < 16; g++) {
        uint32_t bh[4], bl[4];
        uint32_t brow = ((lid >> 4) << 3) + (lid & 7);
        uint32_t baddr = smb + SM_W3H + brow * 528 + (g * 16 + (lid & 8)) * 2;
        LDSM4(bh, baddr);
        LDSM4(bl, baddr + (SM_W3L - SM_W3H));
        MMA(d3a, a3h[g], bh[0], bh[1]);
        MMA(d3a, a3h[g], bl[0], bl[1]);
        MMA(d3a, a3l[g], bh[0], bh[1]);
        MMA(d3b, a3h[g], bh[2], bh[3]);
        MMA(d3b, a3h[g], bl[2], bl[3]);
        MMA(d3b, a3l[g], bh[2], bh[3]);
    }

    // ---- epilogue: add b3B, store pB ----
    {
        const float* b3s = (const float*)(sm + SM_B3B);
        float2 bva = *(const float2*)&b3s[cq];
        float2 bvb = *(const float2*)&b3s[8 + cq];
        int r = row0 + slab + r0;
        float2 v;
        v = make_float2(d3a[0] + bva.x, d3a[1] + bva.y);
        *(float2*)&g_pB[r * CD + cq] = v;
        v = make_float2(d3b[0] + bvb.x, d3b[1] + bvb.y);
        *(float2*)&g_pB[r * CD + 8 + cq] = v;
        v = make_float2(d3a[2] + bva.x, d3a[3] + bva.y);
        *(float2*)&g_pB[(r + 8) * CD + cq] = v;
        v = make_float2(d3b[2] + bvb.x, d3b[3] + bvb.y);
        *(float2*)&g_pB[(r + 8) * CD + 8 + cq] = v;
    }
}

// ---------------- k_count: exact while-loop replication -> atomicMax(g_K) ----------------
__global__ void k_count() {
    int row = blockIdx.x * 256 + threadIdx.x;
    const float4* pbp = (const float4*)&g_pB[row * CD];
    float pb[16], u[16];
#pragma unroll
    for (int q = 0; q < 4; q++) {
        float4 v = pbp[q];
        pb[4 * q] = v.x; pb[4 * q + 1] = v.y; pb[4 * q + 2] = v.z; pb[4 * q + 3] = v.w;
    }
#pragma unroll
    for (int j = 0; j < 16; j++) u[j] = 0.0f;

    int i = 0;
    float res = __int_as_float(0x7f800000);
    while (res >= 0.01f && i < 200) {
        float s2 = 0.0f;
#pragma unroll
        for (int j = 0; j < 16; j++) {
            float s  = u[j] + pb[j];
            float un = __fsub_rn(u[j], __fmul_rn(0.1f, s));
            un = fminf(fmaxf(un, -1.0f), 1.0f);
            float dd = un - u[j];
            s2 += dd * dd;
            u[j] = un;
        }
        res = __fdiv_rn(sqrtf(s2), 0.1f);
        i++;
    }
    int v = i;
#pragma unroll
    for (int o = 16; o > 0; o >>= 1)
        v = max(v, __shfl_xor_sync(0xffffffffu, v, o));
    if ((threadIdx.x & 31) == 0) atomicMax(&g_K, v);
}

// ---------------- k_final: u = clamp(-(1 - 0.9^(K+6)) * pB) ----------------
__global__ void k_final(float* __restrict__ out) {
    int row = blockIdx.x * 256 + threadIdx.x;
    int n = g_K + 6;
    float f = -(1.0f - powf(0.9f, (float)n));
    const float4* ip = (const float4*)&g_pB[row * CD];
    float4* op = (float4*)&out[row * CD];
#pragma unroll
    for (int q = 0; q < 4; q++) {
        float4 v = ip[q];
        float4 u;
        u.x = fminf(fmaxf(f * v.x, -1.0f), 1.0f);
        u.y = fminf(fmaxf(f * v.y, -1.0f), 1.0f);
        u.z = fminf(fmaxf(f * v.z, -1.0f), 1.0f);
        u.w = fminf(fmaxf(f * v.w, -1.0f), 1.0f);
        op[q] = u;
    }
}

// ---------------------------------------------------------------------------
extern "C" void kernel_launch(void* const* d_in, const int* in_sizes, int n_in,
                              void* d_out, int out_size) {
    const float* x  = (const float*)d_in[0];
    const float* t  = (const float*)d_in[1];
    const float* W1 = (const float*)d_in[2];
    const float* b1 = (const float*)d_in[3];
    const float* W2 = (const float*)d_in[4];
    const float* b2 = (const float*)d_in[5];
    const float* W3 = (const float*)d_in[6];
    const float* b3 = (const float*)d_in[7];
    const float* Bm = (const float*)d_in[8];
    float* out = (float*)d_out;

    cudaFuncSetAttribute(k_mlp, cudaFuncAttributeMaxDynamicSharedMemorySize, SM_TOTAL);

    k_prep<<<1, 256>>>(W3, b3, Bm);
    k_mlp<<<BATCH / 128, 256, SM_TOTAL>>>(x, t, W1, b1, W2, b2);
    k_count<<<BATCH / 256, 256>>>();
    k_final<<<BATCH / 256, 256>>>(out);
}

// round 7
// speedup vs baseline: 2.2018x; 1.0053x over previous
#include <cuda_runtime.h>
#include <cuda_bf16.h>
#include <math.h>
#include <cstdint>

#define BATCH 131072
#define SD 64
#define CD 16
#define HID 256

// ---------------- smem layout (bytes) ----------------
#define SM_A2H   0         // 128 rows x 264 halves (528B stride) = 67584
#define SM_A2L   67584
#define SM_WH    135168    // 256 n-rows x 72 halves (144B stride) = 36864
#define SM_WL    172032
#define SM_W3H   135168    // reuse W buffer: 16 x 264 halves (528B) = 8448
#define SM_W3L   143616
#define SM_B1    208896    // 256 f32
#define SM_B2    209920    // 256 f32
#define SM_B3B   210944    // 16 f32
#define SM_TOTAL 211008

// ---------------- scratch globals ----------------
__device__ float g_W3B[HID * CD];
__device__ float g_b3B[CD];
__device__ float g_pB[BATCH * CD];
__device__ int   g_K;

// ---------------- helpers ----------------
__device__ __forceinline__ uint32_t smem_u32(const void* p) {
    uint32_t a;
    asm("{ .reg .u64 t; cvta.to.shared.u64 t, %1; cvt.u32.u64 %0, t; }" : "=r"(a) : "l"(p));
    return a;
}

// split (a,b) f32 pair into packed bf16x2 hi + lo (residual)
__device__ __forceinline__ void split2(float a, float b, uint32_t& hi, uint32_t& lo) {
    __nv_bfloat16 ha = __float2bfloat16(a), hb = __float2bfloat16(b);
    float ra = a - __bfloat162float(ha);
    float rb = b - __bfloat162float(hb);
    __nv_bfloat16 la = __float2bfloat16(ra), lb = __float2bfloat16(rb);
    hi = ((uint32_t)__bfloat16_as_ushort(hb) << 16) | (uint32_t)__bfloat16_as_ushort(ha);
    lo = ((uint32_t)__bfloat16_as_ushort(lb) << 16) | (uint32_t)__bfloat16_as_ushort(la);
}

#define LDSM4(v, addr) \
    asm volatile("ldmatrix.sync.aligned.m8n8.x4.shared.b16 {%0,%1,%2,%3}, [%4];" \
        : "=r"((v)[0]), "=r"((v)[1]), "=r"((v)[2]), "=r"((v)[3]) : "r"(addr))

#define MMA(d, a, b0, b1) \
    asm volatile("mma.sync.aligned.m16n8k16.row.col.f32.bf16.bf16.f32 " \
        "{%0,%1,%2,%3}, {%4,%5,%6,%7}, {%8,%9}, {%0,%1,%2,%3};" \
        : "+f"((d)[0]), "+f"((d)[1]), "+f"((d)[2]), "+f"((d)[3]) \
        : "r"((a)[0]), "r"((a)[1]), "r"((a)[2]), "r"((a)[3]), "r"(b0), "r"(b1))

// ---------------- k_prep ----------------
__global__ void k_prep(const float* __restrict__ W3, const float* __restrict__ b3,
                       const float* __restrict__ Bm) {
    int h = threadIdx.x;
    float acc[CD];
#pragma unroll
    for (int j = 0; j < CD; j++) acc[j] = 0.0f;
    for (int d = 0; d < SD; d++) {
        float w = W3[h * SD + d];
#pragma unroll
        for (int j = 0; j < CD; j++) acc[j] += w * Bm[d * CD + j];
    }
#pragma unroll
    for (int j = 0; j < CD; j++) g_W3B[h * CD + j] = acc[j];
    if (h < CD) {
        float a = 0.0f;
        for (int d = 0; d < SD; d++) a += b3[d] * Bm[d * CD + h];
        g_b3B[h] = a;
    }
    if (h == 0) g_K = 0;
}

// coop: stage W chunk [64 k x 256 n] (f32 row-major gmem) -> Wt[n][k] bf16 hi/lo
__device__ __forceinline__ void load_wchunk(char* sm, const float* __restrict__ W,
                                            int krow0, int tid) {
    int n = tid;
#pragma unroll
    for (int it = 0; it < 8; it++) {
        int kb = krow0 + it * 8;
        uint32_t h[4], l[4];
#pragma unroll
        for (int q = 0; q < 4; q++) {
            float w0 = W[(kb + 2 * q) * HID + n];
            float w1 = W[(kb + 2 * q + 1) * HID + n];
            split2(w0, w1, h[q], l[q]);
        }
        *(uint4*)(sm + SM_WH + n * 144 + it * 16) = make_uint4(h[0], h[1], h[2], h[3]);
        *(uint4*)(sm + SM_WL + n * 144 + it * 16) = make_uint4(l[0], l[1], l[2], l[3]);
    }
}

// ---------------- fused MLP via mma.sync (HMMA) ----------------
__global__ void __launch_bounds__(256, 1) k_mlp(
    const float* __restrict__ x, const float* __restrict__ t,
    const float* __restrict__ W1, const float* __restrict__ b1,
    const float* __restrict__ W2, const float* __restrict__ b2)
{
    extern __shared__ char sm[];
    uint32_t smb = smem_u32(sm);
    int tid = threadIdx.x, wid = tid >> 5, lid = tid & 31;
    int slab = wid * 16;
    int row0 = blockIdx.x * 128;
    int r0 = lid >> 2, cq = 2 * (lid & 3);

    // coop: biases + W1 chunk
    float t0 = t[0];
    ((float*)(sm + SM_B1))[tid] = fmaf(t0, W1[64 * HID + tid], b1[tid]);
    ((float*)(sm + SM_B2))[tid] = b2[tid];
    if (tid < CD) ((float*)(sm + SM_B3B))[tid] = g_b3B[tid];
    load_wchunk(sm, W1, 0, tid);

    // per-warp: stage own 16 rows of X (f32) into own A2H slab region, stride 68 f32
    float* Xs = (float*)(sm + SM_A2H + wid * 8448);
#pragma unroll
    for (int i = 0; i < 8; i++) {
        int fid = i * 32 + lid;
        int r = fid >> 4, c4 = fid & 15;
        float4 v = *(const float4*)&x[(row0 + slab + r) * SD + c4 * 4];
        *(float4*)&Xs[r * 68 + c4 * 4] = v;
    }
    __syncwarp();

    // X fragments (hi/lo) in regs: 4 k-tiles
    uint32_t xh[4][4], xl[4][4];
#pragma unroll
    for (int kt = 0; kt < 4; kt++) {
        int cb = kt * 16 + cq;
        float2 v00 = *(float2*)&Xs[r0 * 68 + cb];
        float2 v10 = *(float2*)&Xs[(r0 + 8) * 68 + cb];
        float2 v01 = *(float2*)&Xs[r0 * 68 + cb + 8];
        float2 v11 = *(float2*)&Xs[(r0 + 8) * 68 + cb + 8];
        split2(v00.x, v00.y, xh[kt][0], xl[kt][0]);
        split2(v10.x, v10.y, xh[kt][1], xl[kt][1]);
        split2(v01.x, v01.y, xh[kt][2], xl[kt][2]);
        split2(v11.x, v11.y, xh[kt][3], xl[kt][3]);
    }
    __syncwarp();
    __syncthreads();   // W1 + biases staged; X frag loads done (X region freed)

    // ---- Layer 1: D[16x256] = X @ W1 (3-product) ----
    float d[32][4];
#pragma unroll
    for (int m = 0; m < 32; m++)
#pragma unroll
        for (int q = 0; q < 4; q++) d[m][q] = 0.0f;

#pragma unroll
    for (int kt = 0; kt < 4; kt++) {
#pragma unroll
        for (int n2 = 0; n2 < 16; n2++) {
            uint32_t bh[4], bl[4];
            uint32_t brow = n2 * 16 + ((lid >> 4) << 3) + (lid & 7);
            uint32_t baddr = smb + SM_WH + brow * 144 + (kt * 16 + (lid & 8)) * 2;
            LDSM4(bh, baddr);
            LDSM4(bl, baddr + (SM_WL - SM_WH));
            MMA(d[2 * n2],     xh[kt], bh[0], bh[1]);
            MMA(d[2 * n2],     xh[kt], bl[0], bl[1]);
            MMA(d[2 * n2],     xl[kt], bh[0], bh[1]);
            MMA(d[2 * n2 + 1], xh[kt], bh[2], bh[3]);
            MMA(d[2 * n2 + 1], xh[kt], bl[2], bl[3]);
            MMA(d[2 * n2 + 1], xl[kt], bh[2], bh[3]);
        }
    }

    // ---- relu + bias1 -> A2 (warp-private smem, hi/lo) ----
    {
        const float* bs1 = (const float*)(sm + SM_B1);
#pragma unroll
        for (int m = 0; m < 32; m++) {
            int c = m * 8 + cq;
            float2 bv = *(const float2*)&bs1[c];
            float h0 = fmaxf(d[m][0] + bv.x, 0.0f);
            float h1 = fmaxf(d[m][1] + bv.y, 0.0f);
            float h2 = fmaxf(d[m][2] + bv.x, 0.0f);
            float h3 = fmaxf(d[m][3] + bv.y, 0.0f);
            uint32_t hi01, lo01, hi23, lo23;
            split2(h0, h1, hi01, lo01);
            split2(h2, h3, hi23, lo23);
            int ra = slab + r0;
            *(uint32_t*)(sm + SM_A2H + ra * 528 + c * 2) = hi01;
            *(uint32_t*)(sm + SM_A2L + ra * 528 + c * 2) = lo01;
            *(uint32_t*)(sm + SM_A2H + (ra + 8) * 528 + c * 2) = hi23;
            *(uint32_t*)(sm + SM_A2L + (ra + 8) * 528 + c * 2) = lo23;
        }
    }
    __syncthreads();   // layer1 done everywhere; W buffer free; A2 visible

    // zero accum for layer 2
#pragma unroll
    for (int m = 0; m < 32; m++)
#pragma unroll
        for (int q = 0; q < 4; q++) d[m][q] = 0.0f;

    // ---- Layer 2: 4 K-chunks of 64 ----
#pragma unroll 1
    for (int kc = 0; kc < 4; kc++) {
        load_wchunk(sm, W2, kc * 64, tid);
        __syncthreads();
#pragma unroll
        for (int kt = 0; kt < 4; kt++) {
            uint32_t ah[4], al[4];
            uint32_t arow = slab + (lid & 15);
            uint32_t acol = kc * 64 + kt * 16 + ((lid >> 4) << 3);
            uint32_t aaddr = smb + SM_A2H + arow * 528 + acol * 2;
            LDSM4(ah, aaddr);
            LDSM4(al, aaddr + (SM_A2L - SM_A2H));
#pragma unroll
            for (int n2 = 0; n2 < 16; n2++) {
                uint32_t bh[4], bl[4];
                uint32_t brow = n2 * 16 + ((lid >> 4) << 3) + (lid & 7);
                uint32_t baddr = smb + SM_WH + brow * 144 + (kt * 16 + (lid & 8)) * 2;
                LDSM4(bh, baddr);
                LDSM4(bl, baddr + (SM_WL - SM_WH));
                MMA(d[2 * n2],     ah, bh[0], bh[1]);
                MMA(d[2 * n2],     ah, bl[0], bl[1]);
                MMA(d[2 * n2],     al, bh[0], bh[1]);
                MMA(d[2 * n2 + 1], ah, bh[2], bh[3]);
                MMA(d[2 * n2 + 1], ah, bl[2], bl[3]);
                MMA(d[2 * n2 + 1], al, bh[2], bh[3]);
            }
        }
        __syncthreads();
    }

    // ---- stage W3B^T [16n x 256k] hi/lo into W buffer ----
#pragma unroll
    for (int it = 0; it < 8; it++) {
        int pid = tid + it * 256;          // 2048 (n, k-pair) items
        int n = pid & 15, k2 = pid >> 4;   // k2 0..127
        float v0 = g_W3B[(2 * k2) * CD + n];
        float v1 = g_W3B[(2 * k2 + 1) * CD + n];
        uint32_t hi, lo;
        split2(v0, v1, hi, lo);
        *(uint32_t*)(sm + SM_W3H + n * 528 + k2 * 4) = hi;
        *(uint32_t*)(sm + SM_W3L + n * 528 + k2 * 4) = lo;
    }
    __syncthreads();

    // ---- relu + bias2 -> A3 fragments in regs ----
    uint32_t a3h[16][4], a3l[16][4];
    {
        const float* bs2 = (const float*)(sm + SM_B2);
#pragma unroll
        for (int g = 0; g < 16; g++) {
#pragma unroll
            for (int hh = 0; hh < 2; hh++) {
                int m = 2 * g + hh;
                int c = m * 8 + cq;
                float2 bv = *(const float2*)&bs2[c];
                float h0 = fmaxf(d[m][0] + bv.x, 0.0f);
                float h1 = fmaxf(d[m][1] + bv.y, 0.0f);
                float h2 = fmaxf(d[m][2] + bv.x, 0.0f);
                float h3 = fmaxf(d[m][3] + bv.y, 0.0f);
                split2(h0, h1, a3h[g][2 * hh],     a3l[g][2 * hh]);
                split2(h2, h3, a3h[g][2 * hh + 1], a3l[g][2 * hh + 1]);
            }
        }
    }

    // ---- Layer 3: pB[16x16] = H2 @ W3B ----
    float d3a[4] = {0.f, 0.f, 0.f, 0.f};
    float d3b[4] = {0.f, 0.f, 0.f, 0.f};
#pragma unroll
    for (int g = 0; g < 16; g++) {
        uint32_t bh[4], bl[4];
        uint32_t brow = ((lid >> 4) << 3) + (lid & 7);
        uint32_t baddr = smb + SM_W3H + brow * 528 + (g * 16 + (lid & 8)) * 2;
        LDSM4(bh, baddr);
        LDSM4(bl, baddr + (SM_W3L - SM_W3H));
        MMA(d3a, a3h[g], bh[0], bh[1]);
        MMA(d3a, a3h[g], bl[0], bl[1]);
        MMA(d3a, a3l[g], bh[0], bh[1]);
        MMA(d3b, a3h[g], bh[2], bh[3]);
        MMA(d3b, a3h[g], bl[2], bl[3]);
        MMA(d3b, a3l[g], bh[2], bh[3]);
    }

    // ---- epilogue: add b3B, store pB ----
    {
        const float* b3s = (const float*)(sm + SM_B3B);
        float2 bva = *(const float2*)&b3s[cq];
        float2 bvb = *(const float2*)&b3s[8 + cq];
        int r = row0 + slab + r0;
        float2 v;
        v = make_float2(d3a[0] + bva.x, d3a[1] + bva.y);
        *(float2*)&g_pB[r * CD + cq] = v;
        v = make_float2(d3b[0] + bvb.x, d3b[1] + bvb.y);
        *(float2*)&g_pB[r * CD + 8 + cq] = v;
        v = make_float2(d3a[2] + bva.x, d3a[3] + bva.y);
        *(float2*)&g_pB[(r + 8) * CD + cq] = v;
        v = make_float2(d3b[2] + bvb.x, d3b[3] + bvb.y);
        *(float2*)&g_pB[(r + 8) * CD + 8 + cq] = v;
    }
}

// ---------------- k_count: exact while-loop replication -> atomicMax(g_K) ----------------
__global__ void k_count() {
    int row = blockIdx.x * 256 + threadIdx.x;
    const float4* pbp = (const float4*)&g_pB[row * CD];
    float pb[16], u[16];
#pragma unroll
    for (int q = 0; q < 4; q++) {
        float4 v = pbp[q];
        pb[4 * q] = v.x; pb[4 * q + 1] = v.y; pb[4 * q + 2] = v.z; pb[4 * q + 3] = v.w;
    }
#pragma unroll
    for (int j = 0; j < 16; j++) u[j] = 0.0f;

    int i = 0;
    float res = __int_as_float(0x7f800000);
    while (res >= 0.01f && i < 200) {
        float s2 = 0.0f;
#pragma unroll
        for (int j = 0; j < 16; j++) {
            float s  = u[j] + pb[j];
            float un = __fsub_rn(u[j], __fmul_rn(0.1f, s));
            un = fminf(fmaxf(un, -1.0f), 1.0f);
            float dd = un - u[j];
            s2 += dd * dd;
            u[j] = un;
        }
        res = __fdiv_rn(sqrtf(s2), 0.1f);
        i++;
    }
    int v = i;
#pragma unroll
    for (int o = 16; o > 0; o >>= 1)
        v = max(v, __shfl_xor_sync(0xffffffffu, v, o));
    if ((threadIdx.x & 31) == 0) atomicMax(&g_K, v);
}

// ---------------- k_final: u = clamp(-(1 - 0.9^(K+6)) * pB) ----------------
__global__ void k_final(float* __restrict__ out) {
    int row = blockIdx.x * 256 + threadIdx.x;
    int n = g_K + 6;
    float f = -(1.0f - powf(0.9f, (float)n));
    const float4* ip = (const float4*)&g_pB[row * CD];
    float4* op = (float4*)&out[row * CD];
#pragma unroll
    for (int q = 0; q < 4; q++) {
        float4 v = ip[q];
        float4 u;
        u.x = fminf(fmaxf(f * v.x, -1.0f), 1.0f);
        u.y = fminf(fmaxf(f * v.y, -1.0f), 1.0f);
        u.z = fminf(fmaxf(f * v.z, -1.0f), 1.0f);
        u.w = fminf(fmaxf(f * v.w, -1.0f), 1.0f);
        op[q] = u;
    }
}

// ---------------------------------------------------------------------------
extern "C" void kernel_launch(void* const* d_in, const int* in_sizes, int n_in,
                              void* d_out, int out_size) {
    const float* x  = (const float*)d_in[0];
    const float* t  = (const float*)d_in[1];
    const float* W1 = (const float*)d_in[2];
    const float* b1 = (const float*)d_in[3];
    const float* W2 = (const float*)d_in[4];
    const float* b2 = (const float*)d_in[5];
    const float* W3 = (const float*)d_in[6];
    const float* b3 = (const float*)d_in[7];
    const float* Bm = (const float*)d_in[8];
    float* out = (float*)d_out;

    cudaFuncSetAttribute(k_mlp, cudaFuncAttributeMaxDynamicSharedMemorySize, SM_TOTAL);

    k_prep<<<1, 256>>>(W3, b3, Bm);
    k_mlp<<<BATCH / 128, 256, SM_TOTAL>>>(x, t, W1, b1, W2, b2);
    k_count<<<BATCH / 256, 256>>>();
    k_final<<<BATCH / 256, 256>>>(out);
}